// round 4
// baseline (speedup 1.0000x reference)
#include <cuda_runtime.h>
#include <math_constants.h>

// ---------------------------------------------------------------------------
// DetectionLoss — single persistent kernel, one wave (1536 blocks, 11/SM cap
// via launch_bounds => all co-resident), software grid barrier (monotonic
// ticket, replay-safe), last-block finalize.
//  phase1: per (b,lvl,chunk-of-100) min d2 for all 128 gts; smem xy loaded as
//          ulonglong2 -> direct f32x2 operands (no pack MOVs).
//  phase2: exactly one (lvl,b,n) task per warp: min over chunk mins,
//          first-chunk, exact first-index recovery (bit-identical math),
//          CE (warp logsumexp) + L1, smem partials, 3 global atomics/block.
// ---------------------------------------------------------------------------

#define NLVL 3
#define NB   16
#define NGT  128
#define NC   80
#define HW0  25600
#define HW1  6400
#define HW2  1600
#define CHUNK 100
#define CL0  256
#define CL1  64
#define CL2  16
#define CPB  (CL0 + CL1 + CL2)    // 336
#define NITEMS (NB * CPB)         // 5376
#define MAXCH 256
#define NTASK (NLVL * NB * NGT)   // 6144
#define NBLK 1536                 // 4 warps/block * 1536 = 6144 = NTASK
#define NWARP (NBLK * 4)

__device__ float g_chunkmin[NTASK * MAXCH];
__device__ float g_acc[3];        // zero-init; exch-reset each replay
__device__ unsigned g_bar0;      // monotonic tickets (never reset)
__device__ unsigned g_bar1;

typedef unsigned long long u64;

__device__ __forceinline__ u64 pack2(float lo, float hi) {
    u64 r;
    asm("mov.b64 %0, {%1, %2};" : "=l"(r) : "f"(lo), "f"(hi));
    return r;
}
__device__ __forceinline__ void unpack2(u64 v, float& lo, float& hi) {
    asm("mov.b64 {%0, %1}, %2;" : "=f"(lo), "=f"(hi) : "l"(v));
}
__device__ __forceinline__ u64 add2(u64 a, u64 b) {
    u64 r;
    asm("add.rn.f32x2 %0, %1, %2;" : "=l"(r) : "l"(a), "l"(b));
    return r;
}
__device__ __forceinline__ u64 mul2(u64 a, u64 b) {
    u64 r;
    asm("mul.rn.f32x2 %0, %1, %2;" : "=l"(r) : "l"(a), "l"(b));
    return r;
}
__device__ __forceinline__ u64 fma2(u64 a, u64 b, u64 c) {
    u64 r;
    asm("fma.rn.f32x2 %0, %1, %2, %3;" : "=l"(r) : "l"(a), "l"(b), "l"(c));
    return r;
}

__global__ void __launch_bounds__(128, 11) k_all(
    const float* __restrict__ r0, const float* __restrict__ r1,
    const float* __restrict__ r2, const float* __restrict__ c0,
    const float* __restrict__ c1, const float* __restrict__ c2,
    const float* __restrict__ gtb, const int* __restrict__ lbl,
    float* __restrict__ out) {
    __shared__ __align__(16) float s_ax[CHUNK];
    __shared__ __align__(16) float s_ay[CHUNK];
    __shared__ float s_part[3];

    const int tid = threadIdx.x;

    // ---------------- phase 1: chunk mins ----------------
    for (int item = blockIdx.x; item < NITEMS; item += NBLK) {
        const int b = item / CPB;
        const int r = item % CPB;
        int lvl, chunk, HW;
        const float* reg;
        if (r < CL0)            { lvl = 0; chunk = r;             reg = r0; HW = HW0; }
        else if (r < CL0 + CL1) { lvl = 1; chunk = r - CL0;       reg = r1; HW = HW1; }
        else                    { lvl = 2; chunk = r - CL0 - CL1; reg = r2; HW = HW2; }
        const int cs = chunk * CHUNK;

        __syncthreads();   // protect smem reuse across items
        if (tid < CHUNK) {
            const float4 v = ((const float4*)(reg + ((size_t)b * HW + cs) * 4))[tid];
            s_ax[tid] = v.x;
            s_ay[tid] = v.y;
        }
        __syncthreads();

        const int gt = tid;  // 0..127
        const float2 g = *(const float2*)(gtb + ((size_t)(b * NGT + gt)) * 4);
        const u64 ngx = pack2(-g.x, -g.x);
        const u64 ngy = pack2(-g.y, -g.y);

        float a0 = CUDART_INF_F, a1 = CUDART_INF_F, a2 = CUDART_INF_F, a3 = CUDART_INF_F;
#pragma unroll 5
        for (int i = 0; i < CHUNK; i += 4) {
            // LDS.128 -> two ready f32x2 operands, no pack MOVs
            const ulonglong2 axp = *(const ulonglong2*)(s_ax + i);
            const ulonglong2 ayp = *(const ulonglong2*)(s_ay + i);
            const u64 dx0 = add2(axp.x, ngx);
            const u64 dx1 = add2(axp.y, ngx);
            const u64 dy0 = add2(ayp.x, ngy);
            const u64 dy1 = add2(ayp.y, ngy);
            const u64 p0 = fma2(dy0, dy0, mul2(dx0, dx0));
            const u64 p1 = fma2(dy1, dy1, mul2(dx1, dx1));
            float d0, d1, d2, d3;
            unpack2(p0, d0, d1);
            unpack2(p1, d2, d3);
            a0 = fminf(a0, d0);
            a1 = fminf(a1, d1);
            a2 = fminf(a2, d2);
            a3 = fminf(a3, d3);
        }
        const float m = fminf(fminf(a0, a1), fminf(a2, a3));
        const int task = (lvl * NB + b) * NGT + gt;
        g_chunkmin[(size_t)task * MAXCH + chunk] = m;
    }

    // ---------------- grid barrier (monotonic tickets, load-poll) ----------
    if (tid == 0) {
        __threadfence();
        const unsigned t = atomicAdd(&g_bar0, 1u);
        const unsigned target = (t / NBLK + 1u) * NBLK;
        const volatile unsigned* vb = (const volatile unsigned*)&g_bar0;
        while (*vb < target) __nanosleep(64);
        __threadfence();
    }
    __syncthreads();
    if (tid < 3) s_part[tid] = 0.0f;
    __syncthreads();

    // ---------------- phase 2: one task per warp ----------------
    const int lane = tid & 31;
    {
        const int w   = blockIdx.x * 4 + (tid >> 5);  // 0..6143 == task
        const int lvl = w >> 11;
        const int rr  = w & 2047;
        const int b   = rr >> 7;
        const int n   = rr & 127;
        const int nch = (lvl == 0) ? CL0 : ((lvl == 1) ? CL1 : CL2);

        const size_t tb = (size_t)w * MAXCH;
        float cm[8];
#pragma unroll
        for (int k = 0; k < 8; k++)
            cm[k] = (lane + 32 * k < nch) ? __ldcg(&g_chunkmin[tb + lane + 32 * k])
                                          : CUDART_INF_F;
        float m = cm[0];
#pragma unroll
        for (int k = 1; k < 8; k++) m = fminf(m, cm[k]);
#pragma unroll
        for (int o = 16; o; o >>= 1) m = fminf(m, __shfl_xor_sync(0xFFFFFFFFu, m, o));

        const float wt = (__fsqrt_rn(m) < 2.5f) ? 1.0f : 0.0f;

        int cand = 0x7FFFFFFF;
#pragma unroll
        for (int k = 0; k < 8; k++)
            if (cm[k] == m) cand = min(cand, lane + 32 * k);
#pragma unroll
        for (int o = 16; o; o >>= 1) cand = min(cand, __shfl_xor_sync(0xFFFFFFFFu, cand, o));
        const int cs = cand * CHUNK;

        const float* cls = (lvl == 0) ? c0 : ((lvl == 1) ? c1 : c2);
        const float* reg = (lvl == 0) ? r0 : ((lvl == 1) ? r1 : r2);
        const int    HW  = (lvl == 0) ? HW0 : ((lvl == 1) ? HW1 : HW2);

        // exact first-index recovery (bit-identical arithmetic to phase 1)
        const float2 g = *(const float2*)(gtb + ((size_t)(b * NGT + n)) * 4);
        int midx = 0x7FFFFFFF;
#pragma unroll
        for (int j = 0; j < 4; j++) {
            const int a = lane + 32 * j;
            if (a < CHUNK) {
                const float2 p = *(const float2*)(reg + ((size_t)b * HW + cs + a) * 4);
                const float dx = __fadd_rn(p.x, -g.x);
                const float dy = __fadd_rn(p.y, -g.y);
                const float d2 = __fmaf_rn(dy, dy, __fmul_rn(dx, dx));
                if (d2 == m) midx = min(midx, cs + a);
            }
        }
#pragma unroll
        for (int o = 16; o; o >>= 1) midx = min(midx, __shfl_xor_sync(0xFFFFFFFFu, midx, o));
        const int idx = midx;

        // CE via warp logsumexp over 80 logits
        const float* row = cls + ((size_t)b * HW + idx) * NC;
        const float x0 = row[lane];
        const float x1 = row[lane + 32];
        const float x2 = (lane < 16) ? row[lane + 64] : -CUDART_INF_F;

        float mx = fmaxf(fmaxf(x0, x1), x2);
#pragma unroll
        for (int o = 16; o; o >>= 1) mx = fmaxf(mx, __shfl_xor_sync(0xFFFFFFFFu, mx, o));

        float s = expf(x0 - mx) + expf(x1 - mx) + ((lane < 16) ? expf(x2 - mx) : 0.0f);

        const int label = lbl[rr];
        float xl = 0.0f;
        if (lane == label)           xl = x0;
        else if (lane + 32 == label) xl = x1;
        else if (lane + 64 == label) xl = x2;

#pragma unroll
        for (int o = 16; o; o >>= 1) {
            s  += __shfl_xor_sync(0xFFFFFFFFu, s, o);
            xl += __shfl_xor_sync(0xFFFFFFFFu, xl, o);
        }

        if (lane == 0) {
            const float ce = (mx + logf(s)) - xl;
            const float4 p  = *(const float4*)(reg + ((size_t)b * HW + idx) * 4);
            const float4 gg = *(const float4*)(gtb + ((size_t)(b * NGT + n)) * 4);
            const float l1 = fabsf(p.x - gg.x) + fabsf(p.y - gg.y) +
                             fabsf(p.z - gg.z) + fabsf(p.w - gg.w);
            atomicAdd(&s_part[0], ce * wt);
            atomicAdd(&s_part[1], l1 * wt);
            atomicAdd(&s_part[2], wt);
        }
    }

    // ---------------- block partial -> global, last block finalizes --------
    __syncthreads();
    if (tid == 0) {
        atomicAdd(&g_acc[0], s_part[0]);
        atomicAdd(&g_acc[1], s_part[1]);
        atomicAdd(&g_acc[2], s_part[2]);
        __threadfence();
        const unsigned t2 = atomicAdd(&g_bar1, 1u);
        if (t2 % NBLK == NBLK - 1u) {   // last arriver: all adds visible
            const float a0 = atomicExch(&g_acc[0], 0.0f);
            const float a1 = atomicExch(&g_acc[1], 0.0f);
            const float np = atomicExch(&g_acc[2], 0.0f);
            const float denom = fmaxf(np, 1.0f);
            out[0] = a0 / denom;
            out[1] = a1 / denom;
            out[2] = np;
        }
    }
}

// ---------------------------------------------------------------------------
extern "C" void kernel_launch(void* const* d_in, const int* in_sizes, int n_in,
                              void* d_out, int out_size) {
    const float* c[3] = {0, 0, 0};
    const float* r[3] = {0, 0, 0};
    const float* gtb  = 0;
    const int*   lbl  = 0;
    for (int i = 0; i < n_in; i++) {
        switch (in_sizes[i]) {
            case NB * HW0 * NC: c[0] = (const float*)d_in[i]; break;
            case NB * HW1 * NC: c[1] = (const float*)d_in[i]; break;
            case NB * HW2 * NC: c[2] = (const float*)d_in[i]; break;
            case NB * HW0 * 4:  r[0] = (const float*)d_in[i]; break;
            case NB * HW1 * 4:  r[1] = (const float*)d_in[i]; break;
            case NB * HW2 * 4:  r[2] = (const float*)d_in[i]; break;
            case NB * NGT * 4:  gtb  = (const float*)d_in[i]; break;
            case NB * NGT:      lbl  = (const int*)d_in[i];   break;
        }
    }

    k_all<<<NBLK, 128>>>(r[0], r[1], r[2], c[0], c[1], c[2], gtb, lbl,
                         (float*)d_out);
}

// round 7
// speedup vs baseline: 1.1179x; 1.1179x over previous
#include <cuda_runtime.h>
#include <math_constants.h>

// ---------------------------------------------------------------------------
// DetectionLoss — single persistent kernel, one wave (1184 blocks = 8 x 148,
// exactly 8 blocks/SM => all co-resident), software grid barrier (monotonic
// ticket, replay-safe), last-block finalize.
//  phase1: per (b,lvl,chunk-of-100) min d2 for all 128 gts (packed f32x2),
//          inner loop FULLY unrolled (25 x 4 anchors).
//  phase2: per task-warp: min over chunk mins, first-chunk, exact first-index
//          recovery (bit-identical arithmetic), CE + L1, smem partials.
// ---------------------------------------------------------------------------

#define NLVL 3
#define NB   16
#define NGT  128
#define NC   80
#define HW0  25600
#define HW1  6400
#define HW2  1600
#define CHUNK 100
#define CL0  256
#define CL1  64
#define CL2  16
#define CPB  (CL0 + CL1 + CL2)    // 336
#define NITEMS (NB * CPB)         // 5376
#define MAXCH 256
#define NTASK (NLVL * NB * NGT)   // 6144
#define NBLK 1184                 // 8 * 148 — exactly one wave
#define NWARP (NBLK * 4)          // 4736

__device__ float g_chunkmin[NTASK * MAXCH];
__device__ float g_acc[3];        // zero-init; exch-reset each replay
__device__ unsigned g_bar0;       // monotonic tickets (never reset)
__device__ unsigned g_bar1;

typedef unsigned long long u64;

__device__ __forceinline__ u64 pack2(float lo, float hi) {
    u64 r;
    asm("mov.b64 %0, {%1, %2};" : "=l"(r) : "f"(lo), "f"(hi));
    return r;
}
__device__ __forceinline__ void unpack2(u64 v, float& lo, float& hi) {
    asm("mov.b64 {%0, %1}, %2;" : "=f"(lo), "=f"(hi) : "l"(v));
}
__device__ __forceinline__ u64 add2(u64 a, u64 b) {
    u64 r;
    asm("add.rn.f32x2 %0, %1, %2;" : "=l"(r) : "l"(a), "l"(b));
    return r;
}
__device__ __forceinline__ u64 mul2(u64 a, u64 b) {
    u64 r;
    asm("mul.rn.f32x2 %0, %1, %2;" : "=l"(r) : "l"(a), "l"(b));
    return r;
}
__device__ __forceinline__ u64 fma2(u64 a, u64 b, u64 c) {
    u64 r;
    asm("fma.rn.f32x2 %0, %1, %2, %3;" : "=l"(r) : "l"(a), "l"(b), "l"(c));
    return r;
}

__global__ void __launch_bounds__(128, 10) k_all(
    const float* __restrict__ r0, const float* __restrict__ r1,
    const float* __restrict__ r2, const float* __restrict__ c0,
    const float* __restrict__ c1, const float* __restrict__ c2,
    const float* __restrict__ gtb, const int* __restrict__ lbl,
    float* __restrict__ out) {
    __shared__ __align__(16) float s_ax[CHUNK];
    __shared__ __align__(16) float s_ay[CHUNK];
    __shared__ float s_part[3];

    const int tid = threadIdx.x;

    // ---------------- phase 1: chunk mins ----------------
    for (int item = blockIdx.x; item < NITEMS; item += NBLK) {
        const int b = item / CPB;
        const int r = item % CPB;
        int lvl, chunk, HW;
        const float* reg;
        if (r < CL0)            { lvl = 0; chunk = r;             reg = r0; HW = HW0; }
        else if (r < CL0 + CL1) { lvl = 1; chunk = r - CL0;       reg = r1; HW = HW1; }
        else                    { lvl = 2; chunk = r - CL0 - CL1; reg = r2; HW = HW2; }
        const int cs = chunk * CHUNK;

        __syncthreads();   // protect smem reuse across items
        if (tid < CHUNK) {
            const float4 v = ((const float4*)(reg + ((size_t)b * HW + cs) * 4))[tid];
            s_ax[tid] = v.x;
            s_ay[tid] = v.y;
        }
        __syncthreads();

        const int gt = tid;  // 0..127
        const float2 g = *(const float2*)(gtb + ((size_t)(b * NGT + gt)) * 4);
        const u64 ngx = pack2(-g.x, -g.x);
        const u64 ngy = pack2(-g.y, -g.y);

        float a0 = CUDART_INF_F, a1 = CUDART_INF_F, a2 = CUDART_INF_F, a3 = CUDART_INF_F;
#pragma unroll
        for (int i = 0; i < CHUNK; i += 4) {
            const float4 ax = *(const float4*)(s_ax + i);
            const float4 ay = *(const float4*)(s_ay + i);
            const u64 dx0 = add2(pack2(ax.x, ax.y), ngx);
            const u64 dx1 = add2(pack2(ax.z, ax.w), ngx);
            const u64 dy0 = add2(pack2(ay.x, ay.y), ngy);
            const u64 dy1 = add2(pack2(ay.z, ay.w), ngy);
            const u64 p0 = fma2(dy0, dy0, mul2(dx0, dx0));
            const u64 p1 = fma2(dy1, dy1, mul2(dx1, dx1));
            float d0, d1, d2, d3;
            unpack2(p0, d0, d1);
            unpack2(p1, d2, d3);
            a0 = fminf(a0, d0);
            a1 = fminf(a1, d1);
            a2 = fminf(a2, d2);
            a3 = fminf(a3, d3);
        }
        const float m = fminf(fminf(a0, a1), fminf(a2, a3));
        const int task = (lvl * NB + b) * NGT + gt;
        g_chunkmin[(size_t)task * MAXCH + chunk] = m;
    }

    // ---------------- grid barrier (monotonic tickets) ----------------
    if (tid == 0) {
        __threadfence();
        const unsigned t = atomicAdd(&g_bar0, 1u);
        const unsigned target = (t / NBLK + 1u) * NBLK;
        while (atomicAdd(&g_bar0, 0u) < target) __nanosleep(128);
        __threadfence();
    }
    __syncthreads();
    if (tid < 3) s_part[tid] = 0.0f;
    __syncthreads();

    // ---------------- phase 2: loss per task ----------------
    const int lane = tid & 31;
    const int gw   = blockIdx.x * 4 + (tid >> 5);
    for (int w = gw; w < NTASK; w += NWARP) {
        const int lvl = w >> 11;
        const int rr  = w & 2047;
        const int b   = rr >> 7;
        const int n   = rr & 127;
        const int nch = (lvl == 0) ? CL0 : ((lvl == 1) ? CL1 : CL2);

        const size_t tb = (size_t)w * MAXCH;
        float cm[8];
#pragma unroll
        for (int k = 0; k < 8; k++)
            cm[k] = (lane + 32 * k < nch) ? __ldcg(&g_chunkmin[tb + lane + 32 * k])
                                          : CUDART_INF_F;
        float m = cm[0];
#pragma unroll
        for (int k = 1; k < 8; k++) m = fminf(m, cm[k]);
#pragma unroll
        for (int o = 16; o; o >>= 1) m = fminf(m, __shfl_xor_sync(0xFFFFFFFFu, m, o));

        const float wt = (__fsqrt_rn(m) < 2.5f) ? 1.0f : 0.0f;

        int cand = 0x7FFFFFFF;
#pragma unroll
        for (int k = 0; k < 8; k++)
            if (cm[k] == m) cand = min(cand, lane + 32 * k);
#pragma unroll
        for (int o = 16; o; o >>= 1) cand = min(cand, __shfl_xor_sync(0xFFFFFFFFu, cand, o));
        const int cs = cand * CHUNK;

        const float* cls = (lvl == 0) ? c0 : ((lvl == 1) ? c1 : c2);
        const float* reg = (lvl == 0) ? r0 : ((lvl == 1) ? r1 : r2);
        const int    HW  = (lvl == 0) ? HW0 : ((lvl == 1) ? HW1 : HW2);

        // exact first-index recovery (bit-identical arithmetic to phase 1)
        const float2 g = *(const float2*)(gtb + ((size_t)(b * NGT + n)) * 4);
        int midx = 0x7FFFFFFF;
#pragma unroll
        for (int j = 0; j < 4; j++) {
            const int a = lane + 32 * j;
            if (a < CHUNK) {
                const float2 p = *(const float2*)(reg + ((size_t)b * HW + cs + a) * 4);
                const float dx = __fadd_rn(p.x, -g.x);
                const float dy = __fadd_rn(p.y, -g.y);
                const float d2 = __fmaf_rn(dy, dy, __fmul_rn(dx, dx));
                if (d2 == m) midx = min(midx, cs + a);
            }
        }
#pragma unroll
        for (int o = 16; o; o >>= 1) midx = min(midx, __shfl_xor_sync(0xFFFFFFFFu, midx, o));
        const int idx = midx;

        // CE via warp logsumexp over 80 logits
        const float* row = cls + ((size_t)b * HW + idx) * NC;
        const float x0 = row[lane];
        const float x1 = row[lane + 32];
        const float x2 = (lane < 16) ? row[lane + 64] : -CUDART_INF_F;

        float mx = fmaxf(fmaxf(x0, x1), x2);
#pragma unroll
        for (int o = 16; o; o >>= 1) mx = fmaxf(mx, __shfl_xor_sync(0xFFFFFFFFu, mx, o));

        float s = expf(x0 - mx) + expf(x1 - mx) + ((lane < 16) ? expf(x2 - mx) : 0.0f);

        const int label = lbl[rr];
        float xl = 0.0f;
        if (lane == label)           xl = x0;
        else if (lane + 32 == label) xl = x1;
        else if (lane + 64 == label) xl = x2;

#pragma unroll
        for (int o = 16; o; o >>= 1) {
            s  += __shfl_xor_sync(0xFFFFFFFFu, s, o);
            xl += __shfl_xor_sync(0xFFFFFFFFu, xl, o);
        }

        if (lane == 0) {
            const float ce = (mx + logf(s)) - xl;
            const float4 p  = *(const float4*)(reg + ((size_t)b * HW + idx) * 4);
            const float4 gg = *(const float4*)(gtb + ((size_t)(b * NGT + n)) * 4);
            const float l1 = fabsf(p.x - gg.x) + fabsf(p.y - gg.y) +
                             fabsf(p.z - gg.z) + fabsf(p.w - gg.w);
            atomicAdd(&s_part[0], ce * wt);
            atomicAdd(&s_part[1], l1 * wt);
            atomicAdd(&s_part[2], wt);
        }
    }

    // ---------------- block partial -> global, last block finalizes --------
    __syncthreads();
    if (tid == 0) {
        atomicAdd(&g_acc[0], s_part[0]);
        atomicAdd(&g_acc[1], s_part[1]);
        atomicAdd(&g_acc[2], s_part[2]);
        __threadfence();
        const unsigned t2 = atomicAdd(&g_bar1, 1u);
        if (t2 % NBLK == NBLK - 1u) {   // last arriver: all adds visible
            const float a0 = atomicExch(&g_acc[0], 0.0f);
            const float a1 = atomicExch(&g_acc[1], 0.0f);
            const float np = atomicExch(&g_acc[2], 0.0f);
            const float denom = fmaxf(np, 1.0f);
            out[0] = a0 / denom;
            out[1] = a1 / denom;
            out[2] = np;
        }
    }
}

// ---------------------------------------------------------------------------
extern "C" void kernel_launch(void* const* d_in, const int* in_sizes, int n_in,
                              void* d_out, int out_size) {
    const float* c[3] = {0, 0, 0};
    const float* r[3] = {0, 0, 0};
    const float* gtb  = 0;
    const int*   lbl  = 0;
    for (int i = 0; i < n_in; i++) {
        switch (in_sizes[i]) {
            case NB * HW0 * NC: c[0] = (const float*)d_in[i]; break;
            case NB * HW1 * NC: c[1] = (const float*)d_in[i]; break;
            case NB * HW2 * NC: c[2] = (const float*)d_in[i]; break;
            case NB * HW0 * 4:  r[0] = (const float*)d_in[i]; break;
            case NB * HW1 * 4:  r[1] = (const float*)d_in[i]; break;
            case NB * HW2 * 4:  r[2] = (const float*)d_in[i]; break;
            case NB * NGT * 4:  gtb  = (const float*)d_in[i]; break;
            case NB * NGT:      lbl  = (const int*)d_in[i];   break;
        }
    }

    k_all<<<NBLK, 128>>>(r[0], r[1], r[2], c[0], c[1], c[2], gtb, lbl,
                         (float*)d_out);
}

// round 8
// speedup vs baseline: 1.1683x; 1.0450x over previous
#include <cuda_runtime.h>
#include <math_constants.h>

// ---------------------------------------------------------------------------
// DetectionLoss — single persistent kernel, one wave (1184 blocks = 8 x 148,
// exactly 8 blocks/SM => all co-resident), software grid barrier (monotonic
// ticket, replay-safe, VOLATILE-LOAD poll — no RMW spam on the L2 atomic ALU),
// last-block finalize.
//  phase1: per (b,lvl,chunk-of-100) min d2 for all 128 gts (packed f32x2),
//          inner loop fully unrolled (25 x 4 anchors).
//  phase2: per task-warp: min over chunk mins, first-chunk, exact first-index
//          recovery (bit-identical arithmetic), CE + L1, smem partials.
// ---------------------------------------------------------------------------

#define NLVL 3
#define NB   16
#define NGT  128
#define NC   80
#define HW0  25600
#define HW1  6400
#define HW2  1600
#define CHUNK 100
#define CL0  256
#define CL1  64
#define CL2  16
#define CPB  (CL0 + CL1 + CL2)    // 336
#define NITEMS (NB * CPB)         // 5376
#define MAXCH 256
#define NTASK (NLVL * NB * NGT)   // 6144
#define NBLK 1184                 // 8 * 148 — exactly one wave
#define NWARP (NBLK * 4)          // 4736

__device__ float g_chunkmin[NTASK * MAXCH];
__device__ float g_acc[3];        // zero-init; exch-reset each replay
__device__ unsigned g_bar0;       // monotonic tickets (never reset)
__device__ unsigned g_bar1;

typedef unsigned long long u64;

__device__ __forceinline__ u64 pack2(float lo, float hi) {
    u64 r;
    asm("mov.b64 %0, {%1, %2};" : "=l"(r) : "f"(lo), "f"(hi));
    return r;
}
__device__ __forceinline__ void unpack2(u64 v, float& lo, float& hi) {
    asm("mov.b64 {%0, %1}, %2;" : "=f"(lo), "=f"(hi) : "l"(v));
}
__device__ __forceinline__ u64 add2(u64 a, u64 b) {
    u64 r;
    asm("add.rn.f32x2 %0, %1, %2;" : "=l"(r) : "l"(a), "l"(b));
    return r;
}
__device__ __forceinline__ u64 mul2(u64 a, u64 b) {
    u64 r;
    asm("mul.rn.f32x2 %0, %1, %2;" : "=l"(r) : "l"(a), "l"(b));
    return r;
}
__device__ __forceinline__ u64 fma2(u64 a, u64 b, u64 c) {
    u64 r;
    asm("fma.rn.f32x2 %0, %1, %2, %3;" : "=l"(r) : "l"(a), "l"(b), "l"(c));
    return r;
}

__global__ void __launch_bounds__(128, 10) k_all(
    const float* __restrict__ r0, const float* __restrict__ r1,
    const float* __restrict__ r2, const float* __restrict__ c0,
    const float* __restrict__ c1, const float* __restrict__ c2,
    const float* __restrict__ gtb, const int* __restrict__ lbl,
    float* __restrict__ out) {
    __shared__ __align__(16) float s_ax[CHUNK];
    __shared__ __align__(16) float s_ay[CHUNK];
    __shared__ float s_part[3];

    const int tid = threadIdx.x;

    // ---------------- phase 1: chunk mins ----------------
    for (int item = blockIdx.x; item < NITEMS; item += NBLK) {
        const int b = item / CPB;
        const int r = item % CPB;
        int lvl, chunk, HW;
        const float* reg;
        if (r < CL0)            { lvl = 0; chunk = r;             reg = r0; HW = HW0; }
        else if (r < CL0 + CL1) { lvl = 1; chunk = r - CL0;       reg = r1; HW = HW1; }
        else                    { lvl = 2; chunk = r - CL0 - CL1; reg = r2; HW = HW2; }
        const int cs = chunk * CHUNK;

        __syncthreads();   // protect smem reuse across items
        if (tid < CHUNK) {
            const float4 v = ((const float4*)(reg + ((size_t)b * HW + cs) * 4))[tid];
            s_ax[tid] = v.x;
            s_ay[tid] = v.y;
        }
        __syncthreads();

        const int gt = tid;  // 0..127
        const float2 g = *(const float2*)(gtb + ((size_t)(b * NGT + gt)) * 4);
        const u64 ngx = pack2(-g.x, -g.x);
        const u64 ngy = pack2(-g.y, -g.y);

        float a0 = CUDART_INF_F, a1 = CUDART_INF_F, a2 = CUDART_INF_F, a3 = CUDART_INF_F;
#pragma unroll
        for (int i = 0; i < CHUNK; i += 4) {
            const float4 ax = *(const float4*)(s_ax + i);
            const float4 ay = *(const float4*)(s_ay + i);
            const u64 dx0 = add2(pack2(ax.x, ax.y), ngx);
            const u64 dx1 = add2(pack2(ax.z, ax.w), ngx);
            const u64 dy0 = add2(pack2(ay.x, ay.y), ngy);
            const u64 dy1 = add2(pack2(ay.z, ay.w), ngy);
            const u64 p0 = fma2(dy0, dy0, mul2(dx0, dx0));
            const u64 p1 = fma2(dy1, dy1, mul2(dx1, dx1));
            float d0, d1, d2, d3;
            unpack2(p0, d0, d1);
            unpack2(p1, d2, d3);
            a0 = fminf(a0, d0);
            a1 = fminf(a1, d1);
            a2 = fminf(a2, d2);
            a3 = fminf(a3, d3);
        }
        const float m = fminf(fminf(a0, a1), fminf(a2, a3));
        const int task = (lvl * NB + b) * NGT + gt;
        g_chunkmin[(size_t)task * MAXCH + chunk] = m;
    }

    // -------- grid barrier (monotonic tickets; LOAD-poll, no RMW spam) -----
    if (tid == 0) {
        __threadfence();
        const unsigned t = atomicAdd(&g_bar0, 1u);
        const unsigned target = (t / NBLK + 1u) * NBLK;
        const volatile unsigned* vb = (const volatile unsigned*)&g_bar0;
        while (*vb < target) __nanosleep(128);
        __threadfence();
    }
    __syncthreads();
    if (tid < 3) s_part[tid] = 0.0f;
    __syncthreads();

    // ---------------- phase 2: loss per task ----------------
    const int lane = tid & 31;
    const int gw   = blockIdx.x * 4 + (tid >> 5);
    for (int w = gw; w < NTASK; w += NWARP) {
        const int lvl = w >> 11;
        const int rr  = w & 2047;
        const int b   = rr >> 7;
        const int n   = rr & 127;
        const int nch = (lvl == 0) ? CL0 : ((lvl == 1) ? CL1 : CL2);

        const size_t tb = (size_t)w * MAXCH;
        float cm[8];
#pragma unroll
        for (int k = 0; k < 8; k++)
            cm[k] = (lane + 32 * k < nch) ? __ldcg(&g_chunkmin[tb + lane + 32 * k])
                                          : CUDART_INF_F;
        float m = cm[0];
#pragma unroll
        for (int k = 1; k < 8; k++) m = fminf(m, cm[k]);
#pragma unroll
        for (int o = 16; o; o >>= 1) m = fminf(m, __shfl_xor_sync(0xFFFFFFFFu, m, o));

        const float wt = (__fsqrt_rn(m) < 2.5f) ? 1.0f : 0.0f;

        int cand = 0x7FFFFFFF;
#pragma unroll
        for (int k = 0; k < 8; k++)
            if (cm[k] == m) cand = min(cand, lane + 32 * k);
#pragma unroll
        for (int o = 16; o; o >>= 1) cand = min(cand, __shfl_xor_sync(0xFFFFFFFFu, cand, o));
        const int cs = cand * CHUNK;

        const float* cls = (lvl == 0) ? c0 : ((lvl == 1) ? c1 : c2);
        const float* reg = (lvl == 0) ? r0 : ((lvl == 1) ? r1 : r2);
        const int    HW  = (lvl == 0) ? HW0 : ((lvl == 1) ? HW1 : HW2);

        // exact first-index recovery (bit-identical arithmetic to phase 1)
        const float2 g = *(const float2*)(gtb + ((size_t)(b * NGT + n)) * 4);
        int midx = 0x7FFFFFFF;
#pragma unroll
        for (int j = 0; j < 4; j++) {
            const int a = lane + 32 * j;
            if (a < CHUNK) {
                const float2 p = *(const float2*)(reg + ((size_t)b * HW + cs + a) * 4);
                const float dx = __fadd_rn(p.x, -g.x);
                const float dy = __fadd_rn(p.y, -g.y);
                const float d2 = __fmaf_rn(dy, dy, __fmul_rn(dx, dx));
                if (d2 == m) midx = min(midx, cs + a);
            }
        }
#pragma unroll
        for (int o = 16; o; o >>= 1) midx = min(midx, __shfl_xor_sync(0xFFFFFFFFu, midx, o));
        const int idx = midx;

        // CE via warp logsumexp over 80 logits
        const float* row = cls + ((size_t)b * HW + idx) * NC;
        const float x0 = row[lane];
        const float x1 = row[lane + 32];
        const float x2 = (lane < 16) ? row[lane + 64] : -CUDART_INF_F;

        float mx = fmaxf(fmaxf(x0, x1), x2);
#pragma unroll
        for (int o = 16; o; o >>= 1) mx = fmaxf(mx, __shfl_xor_sync(0xFFFFFFFFu, mx, o));

        float s = expf(x0 - mx) + expf(x1 - mx) + ((lane < 16) ? expf(x2 - mx) : 0.0f);

        const int label = lbl[rr];
        float xl = 0.0f;
        if (lane == label)           xl = x0;
        else if (lane + 32 == label) xl = x1;
        else if (lane + 64 == label) xl = x2;

#pragma unroll
        for (int o = 16; o; o >>= 1) {
            s  += __shfl_xor_sync(0xFFFFFFFFu, s, o);
            xl += __shfl_xor_sync(0xFFFFFFFFu, xl, o);
        }

        if (lane == 0) {
            const float ce = (mx + logf(s)) - xl;
            const float4 p  = *(const float4*)(reg + ((size_t)b * HW + idx) * 4);
            const float4 gg = *(const float4*)(gtb + ((size_t)(b * NGT + n)) * 4);
            const float l1 = fabsf(p.x - gg.x) + fabsf(p.y - gg.y) +
                             fabsf(p.z - gg.z) + fabsf(p.w - gg.w);
            atomicAdd(&s_part[0], ce * wt);
            atomicAdd(&s_part[1], l1 * wt);
            atomicAdd(&s_part[2], wt);
        }
    }

    // ---------------- block partial -> global, last block finalizes --------
    __syncthreads();
    if (tid == 0) {
        atomicAdd(&g_acc[0], s_part[0]);
        atomicAdd(&g_acc[1], s_part[1]);
        atomicAdd(&g_acc[2], s_part[2]);
        __threadfence();
        const unsigned t2 = atomicAdd(&g_bar1, 1u);
        if (t2 % NBLK == NBLK - 1u) {   // last arriver: all adds visible
            const float a0 = atomicExch(&g_acc[0], 0.0f);
            const float a1 = atomicExch(&g_acc[1], 0.0f);
            const float np = atomicExch(&g_acc[2], 0.0f);
            const float denom = fmaxf(np, 1.0f);
            out[0] = a0 / denom;
            out[1] = a1 / denom;
            out[2] = np;
        }
    }
}

// ---------------------------------------------------------------------------
extern "C" void kernel_launch(void* const* d_in, const int* in_sizes, int n_in,
                              void* d_out, int out_size) {
    const float* c[3] = {0, 0, 0};
    const float* r[3] = {0, 0, 0};
    const float* gtb  = 0;
    const int*   lbl  = 0;
    for (int i = 0; i < n_in; i++) {
        switch (in_sizes[i]) {
            case NB * HW0 * NC: c[0] = (const float*)d_in[i]; break;
            case NB * HW1 * NC: c[1] = (const float*)d_in[i]; break;
            case NB * HW2 * NC: c[2] = (const float*)d_in[i]; break;
            case NB * HW0 * 4:  r[0] = (const float*)d_in[i]; break;
            case NB * HW1 * 4:  r[1] = (const float*)d_in[i]; break;
            case NB * HW2 * 4:  r[2] = (const float*)d_in[i]; break;
            case NB * NGT * 4:  gtb  = (const float*)d_in[i]; break;
            case NB * NGT:      lbl  = (const int*)d_in[i];   break;
        }
    }

    k_all<<<NBLK, 128>>>(r[0], r[1], r[2], c[0], c[1], c[2], gtb, lbl,
                         (float*)d_out);
}